// round 3
// baseline (speedup 1.0000x reference)
#include <cuda_runtime.h>
#include <math.h>

#define B      8192
#define H      512
#define V      128
#define STEPS  127
#define R      28      // rows per CTA
#define RP     14      // row pairs per CTA
#define NT     256     // threads per CTA

typedef unsigned long long ull;

// ---------------- device scratch (alloc-free rule: __device__ globals) ----------------
// W4hh[kk][k][g] = W_hh[g*512+k][kk]  (g: 0=i,1=f,2=g,3=o) ; +2048 floats pad for prefetch
__device__ __align__(16) float g_W4hh[H * H * 4 + 2048];
// W4ih[tok][k][g] = W_ih[g*512+k][tok]
__device__ __align__(16) float g_W4ih[V * H * 4];
// WTcz[kk][k] = W_cz[k][kk] ; +H pad for prefetch
__device__ float g_WTcz[H * H + H];
// WTfc[kk][v] = W_fc[v][kk] ; +V pad for prefetch
__device__ float g_WTfc[H * V + V];
// b4[k][g] = b_ih[g*512+k] + b_hh[g*512+k]
__device__ __align__(16) float g_b4[H * 4];

// ---------------- f32x2 packed-math helpers ----------------
__device__ __forceinline__ ull pack2(float lo, float hi) {
    ull r; asm("mov.b64 %0, {%1, %2};" : "=l"(r) : "f"(lo), "f"(hi)); return r;
}
__device__ __forceinline__ void unpack2(ull v, float& lo, float& hi) {
    asm("mov.b64 {%0, %1}, %2;" : "=f"(lo), "=f"(hi) : "l"(v));
}
__device__ __forceinline__ ull fma2(ull a, ull b, ull c) {
    ull d; asm("fma.rn.f32x2 %0, %1, %2, %3;" : "=l"(d) : "l"(a), "l"(b), "l"(c)); return d;
}
__device__ __forceinline__ float sigf(float x) { return 1.0f / (1.0f + expf(-x)); }

// ---------------- prep: weight reshuffles (runs every launch; deterministic) ----------------
__global__ void prep_kernel(const float* __restrict__ W_ih, const float* __restrict__ W_hh,
                            const float* __restrict__ b_ih, const float* __restrict__ b_hh,
                            const float* __restrict__ W_cz, const float* __restrict__ W_fc)
{
    int i = blockIdx.x * blockDim.x + threadIdx.x;
    int stride = gridDim.x * blockDim.x;
    for (int idx = i; idx < H * H * 4; idx += stride) {
        int kk = idx >> 11, rem = idx & 2047;
        int k = rem >> 2, g = rem & 3;
        g_W4hh[idx] = W_hh[(g * H + k) * H + kk];
    }
    for (int idx = i; idx < V * H * 4; idx += stride) {
        int t = idx >> 11, rem = idx & 2047;
        int k = rem >> 2, g = rem & 3;
        g_W4ih[idx] = W_ih[(g * H + k) * V + t];
    }
    for (int idx = i; idx < H * H; idx += stride) {
        int kk = idx >> 9, k = idx & 511;
        g_WTcz[idx] = W_cz[k * H + kk];
    }
    for (int idx = i; idx < H * V; idx += stride) {
        int kk = idx >> 7, v = idx & 127;
        g_WTfc[idx] = W_fc[v * H + kk];
    }
    for (int idx = i; idx < H * 4; idx += stride) {
        int k = idx >> 2, g = idx & 3;
        g_b4[idx] = b_ih[g * H + k] + b_hh[g * H + k];
    }
}

// ---------------- main persistent LSTM kernel ----------------
__global__ __launch_bounds__(NT, 1)
void lstm_main(const float* __restrict__ z, const float* __restrict__ b_cz,
               const float* __restrict__ b_fc, float* __restrict__ out)
{
    extern __shared__ char smem[];
    float2* shA      = (float2*)smem;                 // RP*H  (h buffer, even steps in)
    float2* shB      = shA + RP * H;                  // RP*H  (h buffer, odd steps in)
    float*  sh_logit = (float*)(shB + RP * H);        // R*V
    int*    sh_tok   = (int*)(sh_logit + R * V);      // R

    const int tid  = threadIdx.x;
    const int row0 = blockIdx.x * R;
    if (row0 >= B) return;

    // ---- load z (= h0) into shA, packed as row pairs ----
    for (int idx = tid; idx < RP * H; idx += NT) {
        int rp = idx / H, kk = idx - rp * H;
        int r0 = row0 + 2 * rp;
        float a = (r0     < B) ? z[(size_t)r0 * H + kk]       : 0.f;
        float b = (r0 + 1 < B) ? z[(size_t)(r0 + 1) * H + kk] : 0.f;
        shA[rp * H + kk] = make_float2(a, b);
    }
    if (tid < R) sh_tok[tid] = 0;   // start token one-hot index 0
    __syncthreads();

    // ---- c0 = relu(z @ W_cz^T + b_cz), kept in registers (packed row pairs) ----
    ull c2[2][RP];
    #pragma unroll
    for (int kp = 0; kp < 2; ++kp) {
        const int k = tid + kp * NT;
        ull a[RP];
        float bz = b_cz[k];
        #pragma unroll
        for (int rp = 0; rp < RP; ++rp) a[rp] = pack2(bz, bz);
        const float* wp = g_WTcz + k;
        const ull* hp = (const ull*)shA;
        float w = wp[0];
        for (int kk = 0; kk < H; ++kk) {
            float wn = wp[(kk + 1) * H];   // pad covers kk=511
            ull w2 = pack2(w, w);
            #pragma unroll
            for (int rp = 0; rp < RP; ++rp)
                a[rp] = fma2(hp[rp * H + kk], w2, a[rp]);
            w = wn;
        }
        #pragma unroll
        for (int rp = 0; rp < RP; ++rp) {
            float x0, x1; unpack2(a[rp], x0, x1);
            c2[kp][rp] = pack2(fmaxf(x0, 0.f), fmaxf(x1, 0.f));
        }
    }

    const float4* W4hh = (const float4*)g_W4hh;
    const float4* W4ih = (const float4*)g_W4ih;
    const float4* b4p  = (const float4*)g_b4;

    for (int step = 0; step < STEPS; ++step) {
        float2* hc = (step & 1) ? shB : shA;
        float2* hn = (step & 1) ? shA : shB;
        const ull* hp = (const ull*)hc;
        ull* ho = (ull*)hn;

        // ---- gates + state update: thread owns k (and k+256), all 4 gates, all rows ----
        #pragma unroll
        for (int kp = 0; kp < 2; ++kp) {
            const int k = tid + kp * NT;
            float4 bb = b4p[k];
            ull a0[RP], a1[RP], a2[RP], a3[RP];
            #pragma unroll
            for (int rp = 0; rp < RP; ++rp) {
                float4 wi0 = W4ih[sh_tok[2 * rp] * H + k];       // tok @ W_ih^T via gather
                float4 wi1 = W4ih[sh_tok[2 * rp + 1] * H + k];
                a0[rp] = pack2(bb.x + wi0.x, bb.x + wi1.x);
                a1[rp] = pack2(bb.y + wi0.y, bb.y + wi1.y);
                a2[rp] = pack2(bb.z + wi0.z, bb.z + wi1.z);
                a3[rp] = pack2(bb.w + wi0.w, bb.w + wi1.w);
            }
            const float4* wp = W4hh + k;
            float4 w = wp[0];
            for (int kk = 0; kk < H; ++kk) {
                float4 wnx = wp[(kk + 1) * H];   // pad covers kk=511
                ull wx = pack2(w.x, w.x), wy = pack2(w.y, w.y);
                ull wz = pack2(w.z, w.z), ww = pack2(w.w, w.w);
                #pragma unroll
                for (int rp = 0; rp < RP; ++rp) {
                    ull h2 = hp[rp * H + kk];    // broadcast LDS.64
                    a0[rp] = fma2(h2, wx, a0[rp]);
                    a1[rp] = fma2(h2, wy, a1[rp]);
                    a2[rp] = fma2(h2, wz, a2[rp]);
                    a3[rp] = fma2(h2, ww, a3[rp]);
                }
                w = wnx;
            }
            #pragma unroll
            for (int rp = 0; rp < RP; ++rp) {
                float i0, i1, f0, f1, g0, g1, o0, o1, cc0, cc1;
                unpack2(a0[rp], i0, i1);
                unpack2(a1[rp], f0, f1);
                unpack2(a2[rp], g0, g1);
                unpack2(a3[rp], o0, o1);
                unpack2(c2[kp][rp], cc0, cc1);
                float cn0 = sigf(f0) * cc0 + sigf(i0) * tanhf(g0);
                float cn1 = sigf(f1) * cc1 + sigf(i1) * tanhf(g1);
                float h0v = sigf(o0) * tanhf(cn0);
                float h1v = sigf(o1) * tanhf(cn1);
                c2[kp][rp] = pack2(cn0, cn1);
                ho[rp * H + k] = pack2(h0v, h1v);
            }
        }
        __syncthreads();

        // ---- fc: logits = relu(h_new @ W_fc^T + b_fc); write output + smem ----
        {
            const int v  = tid & (V - 1);
            const int rh = tid >> 7;          // 0 or 1: row-half
            ull fa[7];
            float bv = b_fc[v];
            #pragma unroll
            for (int p = 0; p < 7; ++p) fa[p] = pack2(bv, bv);
            const float* wf = g_WTfc + v;
            const ull* hpn = (const ull*)hn + (size_t)rh * 7 * H;
            float w = wf[0];
            for (int kk = 0; kk < H; ++kk) {
                float wn2 = wf[(kk + 1) * V];  // pad covers kk=511
                ull w2 = pack2(w, w);
                #pragma unroll
                for (int p = 0; p < 7; ++p)
                    fa[p] = fma2(hpn[p * H + kk], w2, fa[p]);
                w = wn2;
            }
            #pragma unroll
            for (int p = 0; p < 7; ++p) {
                float l0, l1; unpack2(fa[p], l0, l1);
                l0 = fmaxf(l0, 0.f); l1 = fmaxf(l1, 0.f);
                int r0 = (rh * 7 + p) * 2;
                sh_logit[r0 * V + v]       = l0;
                sh_logit[(r0 + 1) * V + v] = l1;
                int gr0 = row0 + r0;
                if (gr0     < B) out[((size_t)gr0 * STEPS + step) * V + v]       = l0;
                if (gr0 + 1 < B) out[((size_t)(gr0 + 1) * STEPS + step) * V + v] = l1;
            }
        }
        __syncthreads();

        // ---- greedy argmax per row (lowest index wins ties, matches jnp.argmax) ----
        {
            const int wid = tid >> 5, lane = tid & 31;
            for (int r = wid; r < R; r += 8) {
                float best = -1.f; int bi = 0;
                #pragma unroll
                for (int q = 0; q < 4; ++q) {
                    int vv = lane + 32 * q;
                    float val = sh_logit[r * V + vv];
                    if (val > best) { best = val; bi = vv; }
                }
                #pragma unroll
                for (int off = 16; off; off >>= 1) {
                    float ov = __shfl_xor_sync(0xffffffffu, best, off);
                    int   oi = __shfl_xor_sync(0xffffffffu, bi, off);
                    if (ov > best || (ov == best && oi < bi)) { best = ov; bi = oi; }
                }
                if (lane == 0) sh_tok[r] = bi;
            }
        }
        __syncthreads();
    }
}

// ---------------- launch ----------------
extern "C" void kernel_launch(void* const* d_in, const int* in_sizes, int n_in,
                              void* d_out, int out_size)
{
    const float* z    = (const float*)d_in[0];
    const float* W_ih = (const float*)d_in[1];
    const float* W_hh = (const float*)d_in[2];
    const float* b_ih = (const float*)d_in[3];
    const float* b_hh = (const float*)d_in[4];
    const float* W_cz = (const float*)d_in[5];
    const float* b_cz = (const float*)d_in[6];
    const float* W_fc = (const float*)d_in[7];
    const float* b_fc = (const float*)d_in[8];
    float* out = (float*)d_out;

    prep_kernel<<<1024, 256>>>(W_ih, W_hh, b_ih, b_hh, W_cz, W_fc);

    const int smem_bytes = 2 * RP * H * (int)sizeof(float2)   // h double buffer (112 KB)
                         + R * V * (int)sizeof(float)          // logits (14 KB)
                         + R * (int)sizeof(int);               // tokens
    cudaFuncSetAttribute(lstm_main, cudaFuncAttributeMaxDynamicSharedMemorySize, smem_bytes);
    lstm_main<<<(B + R - 1) / R, NT, smem_bytes>>>(z, b_cz, b_fc, out);
}

// round 7
// speedup vs baseline: 1.5212x; 1.5212x over previous
#include <cuda_runtime.h>
#include <math.h>

#define B      8192
#define H      512
#define V      128
#define STEPS  127
#define R      28      // rows per CTA
#define RP     14      // row pairs per CTA
#define NT     256     // threads per CTA

typedef unsigned long long ull;

// ---------------- device scratch (alloc-free rule: __device__ globals) ----------------
// W4hh[kk][k][g] = W_hh[g*512+k][kk]  (g: 0=i,1=f,2=g,3=o) ; +2048 floats pad for prefetch
__device__ __align__(16) float g_W4hh[H * H * 4 + 2048];
// W4ih[tok][k][g] = W_ih[g*512+k][tok]
__device__ __align__(16) float g_W4ih[V * H * 4];
// WTcz[kk][k] = W_cz[k][kk] ; +H pad for prefetch
__device__ float g_WTcz[H * H + H];
// WTfc[kk][v] = W_fc[v][kk] ; +V pad for prefetch
__device__ float g_WTfc[H * V + V];
// b4[k][g] = b_ih[g*512+k] + b_hh[g*512+k]
__device__ __align__(16) float g_b4[H * 4];

// ---------------- f32x2 packed-math helpers ----------------
__device__ __forceinline__ ull pack2(float lo, float hi) {
    ull r; asm("mov.b64 %0, {%1, %2};" : "=l"(r) : "f"(lo), "f"(hi)); return r;
}
__device__ __forceinline__ void unpack2(ull v, float& lo, float& hi) {
    asm("mov.b64 {%0, %1}, %2;" : "=f"(lo), "=f"(hi) : "l"(v));
}
__device__ __forceinline__ ull fma2(ull a, ull b, ull c) {
    ull d; asm("fma.rn.f32x2 %0, %1, %2, %3;" : "=l"(d) : "l"(a), "l"(b), "l"(c)); return d;
}
__device__ __forceinline__ float sigf(float x) { return 1.0f / (1.0f + expf(-x)); }

// ---------------- prep: weight reshuffles (runs every launch; deterministic) ----------------
__global__ void prep_kernel(const float* __restrict__ W_ih, const float* __restrict__ W_hh,
                            const float* __restrict__ b_ih, const float* __restrict__ b_hh,
                            const float* __restrict__ W_cz, const float* __restrict__ W_fc)
{
    int i = blockIdx.x * blockDim.x + threadIdx.x;
    int stride = gridDim.x * blockDim.x;
    for (int idx = i; idx < H * H * 4; idx += stride) {
        int kk = idx >> 11, rem = idx & 2047;
        int k = rem >> 2, g = rem & 3;
        g_W4hh[idx] = W_hh[(g * H + k) * H + kk];
    }
    for (int idx = i; idx < V * H * 4; idx += stride) {
        int t = idx >> 11, rem = idx & 2047;
        int k = rem >> 2, g = rem & 3;
        g_W4ih[idx] = W_ih[(g * H + k) * V + t];
    }
    for (int idx = i; idx < H * H; idx += stride) {
        int kk = idx >> 9, k = idx & 511;
        g_WTcz[idx] = W_cz[k * H + kk];
    }
    for (int idx = i; idx < H * V; idx += stride) {
        int kk = idx >> 7, v = idx & 127;
        g_WTfc[idx] = W_fc[v * H + kk];
    }
    for (int idx = i; idx < H * 4; idx += stride) {
        int k = idx >> 2, g = idx & 3;
        g_b4[idx] = b_ih[g * H + k] + b_hh[g * H + k];
    }
}

// ---------------- main persistent LSTM kernel ----------------
__global__ __launch_bounds__(NT, 1)
void lstm_main(const float* __restrict__ z, const float* __restrict__ b_cz,
               const float* __restrict__ b_fc, float* __restrict__ out)
{
    extern __shared__ char smem[];
    float2* shA      = (float2*)smem;                 // RP*H  (h buffer, even steps in)
    float2* shB      = shA + RP * H;                  // RP*H  (h buffer, odd steps in)
    float*  sh_logit = (float*)(shB + RP * H);        // R*V
    int*    sh_tok   = (int*)(sh_logit + R * V);      // R

    const int tid  = threadIdx.x;
    const int row0 = blockIdx.x * R;
    if (row0 >= B) return;

    // ---- load z (= h0) into shA, packed as row pairs ----
    for (int idx = tid; idx < RP * H; idx += NT) {
        int rp = idx / H, kk = idx - rp * H;
        int r0 = row0 + 2 * rp;
        float a = (r0     < B) ? z[(size_t)r0 * H + kk]       : 0.f;
        float b = (r0 + 1 < B) ? z[(size_t)(r0 + 1) * H + kk] : 0.f;
        shA[rp * H + kk] = make_float2(a, b);
    }
    if (tid < R) sh_tok[tid] = 0;   // start token one-hot index 0
    __syncthreads();

    // ---- c0 = relu(z @ W_cz^T + b_cz), kept in registers (packed row pairs) ----
    ull c2[2][RP];
    #pragma unroll
    for (int kp = 0; kp < 2; ++kp) {
        const int k = tid + kp * NT;
        ull a[RP];
        float bz = b_cz[k];
        #pragma unroll
        for (int rp = 0; rp < RP; ++rp) a[rp] = pack2(bz, bz);
        const float* wp = g_WTcz + k;
        const ull* hp = (const ull*)shA;
        float w = wp[0];
        for (int kk = 0; kk < H; ++kk) {
            float wn = wp[(kk + 1) * H];   // pad covers kk=511
            ull w2 = pack2(w, w);
            #pragma unroll
            for (int rp = 0; rp < RP; ++rp)
                a[rp] = fma2(hp[rp * H + kk], w2, a[rp]);
            w = wn;
        }
        #pragma unroll
        for (int rp = 0; rp < RP; ++rp) {
            float x0, x1; unpack2(a[rp], x0, x1);
            c2[kp][rp] = pack2(fmaxf(x0, 0.f), fmaxf(x1, 0.f));
        }
    }

    const float4* W4hh = (const float4*)g_W4hh;
    const float4* W4ih = (const float4*)g_W4ih;
    const float4* b4p  = (const float4*)g_b4;

    for (int step = 0; step < STEPS; ++step) {
        float2* hc = (step & 1) ? shB : shA;
        float2* hn = (step & 1) ? shA : shB;
        const ull* hp = (const ull*)hc;
        ull* ho = (ull*)hn;

        // ---- gates + state update: thread owns k (and k+256), all 4 gates, all rows ----
        #pragma unroll
        for (int kp = 0; kp < 2; ++kp) {
            const int k = tid + kp * NT;
            float4 bb = b4p[k];
            ull a0[RP], a1[RP], a2[RP], a3[RP];
            #pragma unroll
            for (int rp = 0; rp < RP; ++rp) {
                float4 wi0 = W4ih[sh_tok[2 * rp] * H + k];       // tok @ W_ih^T via gather
                float4 wi1 = W4ih[sh_tok[2 * rp + 1] * H + k];
                a0[rp] = pack2(bb.x + wi0.x, bb.x + wi1.x);
                a1[rp] = pack2(bb.y + wi0.y, bb.y + wi1.y);
                a2[rp] = pack2(bb.z + wi0.z, bb.z + wi1.z);
                a3[rp] = pack2(bb.w + wi0.w, bb.w + wi1.w);
            }
            const float4* wp = W4hh + k;
            float4 w = wp[0];
            for (int kk = 0; kk < H; ++kk) {
                float4 wnx = wp[(kk + 1) * H];   // pad covers kk=511
                ull wx = pack2(w.x, w.x), wy = pack2(w.y, w.y);
                ull wz = pack2(w.z, w.z), ww = pack2(w.w, w.w);
                #pragma unroll
                for (int rp = 0; rp < RP; ++rp) {
                    ull h2 = hp[rp * H + kk];    // broadcast LDS.64
                    a0[rp] = fma2(h2, wx, a0[rp]);
                    a1[rp] = fma2(h2, wy, a1[rp]);
                    a2[rp] = fma2(h2, wz, a2[rp]);
                    a3[rp] = fma2(h2, ww, a3[rp]);
                }
                w = wnx;
            }
            #pragma unroll
            for (int rp = 0; rp < RP; ++rp) {
                float i0, i1, f0, f1, g0, g1, o0, o1, cc0, cc1;
                unpack2(a0[rp], i0, i1);
                unpack2(a1[rp], f0, f1);
                unpack2(a2[rp], g0, g1);
                unpack2(a3[rp], o0, o1);
                unpack2(c2[kp][rp], cc0, cc1);
                float cn0 = sigf(f0) * cc0 + sigf(i0) * tanhf(g0);
                float cn1 = sigf(f1) * cc1 + sigf(i1) * tanhf(g1);
                float h0v = sigf(o0) * tanhf(cn0);
                float h1v = sigf(o1) * tanhf(cn1);
                c2[kp][rp] = pack2(cn0, cn1);
                ho[rp * H + k] = pack2(h0v, h1v);
            }
        }
        __syncthreads();

        // ---- fc: logits = relu(h_new @ W_fc^T + b_fc); write output + smem ----
        {
            const int v  = tid & (V - 1);
            const int rh = tid >> 7;          // 0 or 1: row-half
            ull fa[7];
            float bv = b_fc[v];
            #pragma unroll
            for (int p = 0; p < 7; ++p) fa[p] = pack2(bv, bv);
            const float* wf = g_WTfc + v;
            const ull* hpn = (const ull*)hn + (size_t)rh * 7 * H;
            float w = wf[0];
            for (int kk = 0; kk < H; ++kk) {
                float wn2 = wf[(kk + 1) * V];  // pad covers kk=511
                ull w2 = pack2(w, w);
                #pragma unroll
                for (int p = 0; p < 7; ++p)
                    fa[p] = fma2(hpn[p * H + kk], w2, fa[p]);
                w = wn2;
            }
            #pragma unroll
            for (int p = 0; p < 7; ++p) {
                float l0, l1; unpack2(fa[p], l0, l1);
                l0 = fmaxf(l0, 0.f); l1 = fmaxf(l1, 0.f);
                int r0 = (rh * 7 + p) * 2;
                sh_logit[r0 * V + v]       = l0;
                sh_logit[(r0 + 1) * V + v] = l1;
                int gr0 = row0 + r0;
                if (gr0     < B) out[((size_t)gr0 * STEPS + step) * V + v]       = l0;
                if (gr0 + 1 < B) out[((size_t)(gr0 + 1) * STEPS + step) * V + v] = l1;
            }
        }
        __syncthreads();

        // ---- greedy argmax per row (lowest index wins ties, matches jnp.argmax) ----
        {
            const int wid = tid >> 5, lane = tid & 31;
            for (int r = wid; r < R; r += 8) {
                float best = -1.f; int bi = 0;
                #pragma unroll
                for (int q = 0; q < 4; ++q) {
                    int vv = lane + 32 * q;
                    float val = sh_logit[r * V + vv];
                    if (val > best) { best = val; bi = vv; }
                }
                #pragma unroll
                for (int off = 16; off; off >>= 1) {
                    float ov = __shfl_xor_sync(0xffffffffu, best, off);
                    int   oi = __shfl_xor_sync(0xffffffffu, bi, off);
                    if (ov > best || (ov == best && oi < bi)) { best = ov; bi = oi; }
                }
                if (lane == 0) sh_tok[r] = bi;
            }
        }
        __syncthreads();
    }
}

// ---------------- launch ----------------
extern "C" void kernel_launch(void* const* d_in, const int* in_sizes, int n_in,
                              void* d_out, int out_size)
{
    const float* z    = (const float*)d_in[0];
    const float* W_ih = (const float*)d_in[1];
    const float* W_hh = (const float*)d_in[2];
    const float* b_ih = (const float*)d_in[3];
    const float* b_hh = (const float*)d_in[4];
    const float* W_cz = (const float*)d_in[5];
    const float* b_cz = (const float*)d_in[6];
    const float* W_fc = (const float*)d_in[7];
    const float* b_fc = (const float*)d_in[8];
    float* out = (float*)d_out;

    prep_kernel<<<1024, 256>>>(W_ih, W_hh, b_ih, b_hh, W_cz, W_fc);

    const int smem_bytes = 2 * RP * H * (int)sizeof(float2)   // h double buffer (112 KB)
                         + R * V * (int)sizeof(float)          // logits (14 KB)
                         + R * (int)sizeof(int);               // tokens
    cudaFuncSetAttribute(lstm_main, cudaFuncAttributeMaxDynamicSharedMemorySize, smem_bytes);
    lstm_main<<<(B + R - 1) / R, NT, smem_bytes>>>(z, b_cz, b_fc, out);
}

// round 9
// speedup vs baseline: 1.7938x; 1.1792x over previous
#include <cuda_runtime.h>
#include <math.h>

#define B      8192
#define H      512
#define V      128
#define STEPS  127
#define R      14      // rows per CTA (halved vs R6 -> 2 CTAs/SM)
#define RP     7       // row pairs per CTA
#define NT     256     // threads per CTA

typedef unsigned long long ull;

// ---------------- device scratch (alloc-free rule: __device__ globals) ----------------
// W4hh[kk][k][g] = W_hh[g*512+k][kk]  (g: 0=i,1=f,2=g,3=o) ; +2048 floats pad for prefetch
__device__ __align__(16) float g_W4hh[H * H * 4 + 2048];
// W4ih[tok][k][g] = W_ih[g*512+k][tok]
__device__ __align__(16) float g_W4ih[V * H * 4];
// WTcz[kk][k] = W_cz[k][kk] ; +H pad for prefetch
__device__ float g_WTcz[H * H + H];
// WTfc[kk][v] = W_fc[v][kk] ; +V pad for prefetch
__device__ float g_WTfc[H * V + V];
// b4[k][g] = b_ih[g*512+k] + b_hh[g*512+k]
__device__ __align__(16) float g_b4[H * 4];

// ---------------- f32x2 packed-math helpers ----------------
__device__ __forceinline__ ull pack2(float lo, float hi) {
    ull r; asm("mov.b64 %0, {%1, %2};" : "=l"(r) : "f"(lo), "f"(hi)); return r;
}
__device__ __forceinline__ void unpack2(ull v, float& lo, float& hi) {
    asm("mov.b64 {%0, %1}, %2;" : "=f"(lo), "=f"(hi) : "l"(v));
}
__device__ __forceinline__ ull fma2(ull a, ull b, ull c) {
    ull d; asm("fma.rn.f32x2 %0, %1, %2, %3;" : "=l"(d) : "l"(a), "l"(b), "l"(c)); return d;
}
__device__ __forceinline__ float sigf(float x) { return 1.0f / (1.0f + expf(-x)); }

// ---------------- prep: weight reshuffles (runs every launch; deterministic) ----------------
__global__ void prep_kernel(const float* __restrict__ W_ih, const float* __restrict__ W_hh,
                            const float* __restrict__ b_ih, const float* __restrict__ b_hh,
                            const float* __restrict__ W_cz, const float* __restrict__ W_fc)
{
    int i = blockIdx.x * blockDim.x + threadIdx.x;
    int stride = gridDim.x * blockDim.x;
    for (int idx = i; idx < H * H * 4; idx += stride) {
        int kk = idx >> 11, rem = idx & 2047;
        int k = rem >> 2, g = rem & 3;
        g_W4hh[idx] = W_hh[(g * H + k) * H + kk];
    }
    for (int idx = i; idx < V * H * 4; idx += stride) {
        int t = idx >> 11, rem = idx & 2047;
        int k = rem >> 2, g = rem & 3;
        g_W4ih[idx] = W_ih[(g * H + k) * V + t];
    }
    for (int idx = i; idx < H * H; idx += stride) {
        int kk = idx >> 9, k = idx & 511;
        g_WTcz[idx] = W_cz[k * H + kk];
    }
    for (int idx = i; idx < H * V; idx += stride) {
        int kk = idx >> 7, v = idx & 127;
        g_WTfc[idx] = W_fc[v * H + kk];
    }
    for (int idx = i; idx < H * 4; idx += stride) {
        int k = idx >> 2, g = idx & 3;
        g_b4[idx] = b_ih[g * H + k] + b_hh[g * H + k];
    }
}

// ---------------- main persistent LSTM kernel (2 CTAs/SM) ----------------
__global__ __launch_bounds__(NT, 2)
void lstm_main(const float* __restrict__ z, const float* __restrict__ b_cz,
               const float* __restrict__ b_fc, float* __restrict__ out)
{
    extern __shared__ char smem[];
    float2* shA      = (float2*)smem;                 // RP*H  (h buffer, even steps in)
    float2* shB      = shA + RP * H;                  // RP*H  (h buffer, odd steps in)
    float*  sh_logit = (float*)(shB + RP * H);        // R*V
    int*    sh_tok   = (int*)(sh_logit + R * V);      // R

    const int tid  = threadIdx.x;
    const int row0 = blockIdx.x * R;
    if (row0 >= B) return;

    // ---- load z (= h0) into shA, packed as row pairs ----
    for (int idx = tid; idx < RP * H; idx += NT) {
        int rp = idx / H, kk = idx - rp * H;
        int r0 = row0 + 2 * rp;
        float a = (r0     < B) ? z[(size_t)r0 * H + kk]       : 0.f;
        float b = (r0 + 1 < B) ? z[(size_t)(r0 + 1) * H + kk] : 0.f;
        shA[rp * H + kk] = make_float2(a, b);
    }
    if (tid < R) sh_tok[tid] = 0;   // start token one-hot index 0
    __syncthreads();

    // ---- c0 = relu(z @ W_cz^T + b_cz), kept in registers (packed row pairs) ----
    ull c2[2][RP];
    #pragma unroll
    for (int kp = 0; kp < 2; ++kp) {
        const int k = tid + kp * NT;
        ull a[RP];
        float bz = b_cz[k];
        #pragma unroll
        for (int rp = 0; rp < RP; ++rp) a[rp] = pack2(bz, bz);
        const float* wp = g_WTcz + k;
        const ull* hp = (const ull*)shA;
        float w = wp[0];
        for (int kk = 0; kk < H; ++kk) {
            float wn = wp[(kk + 1) * H];   // pad covers kk=511
            ull w2 = pack2(w, w);
            #pragma unroll
            for (int rp = 0; rp < RP; ++rp)
                a[rp] = fma2(hp[rp * H + kk], w2, a[rp]);
            w = wn;
        }
        #pragma unroll
        for (int rp = 0; rp < RP; ++rp) {
            float x0, x1; unpack2(a[rp], x0, x1);
            c2[kp][rp] = pack2(fmaxf(x0, 0.f), fmaxf(x1, 0.f));
        }
    }

    const float4* W4hh = (const float4*)g_W4hh;
    const float4* W4ih = (const float4*)g_W4ih;
    const float4* b4p  = (const float4*)g_b4;

    for (int step = 0; step < STEPS; ++step) {
        float2* hc = (step & 1) ? shB : shA;
        float2* hn = (step & 1) ? shA : shB;
        const ull* hp = (const ull*)hc;
        ull* ho = (ull*)hn;

        // ---- gates + state update: thread owns k (and k+256), all 4 gates, all rows ----
        #pragma unroll
        for (int kp = 0; kp < 2; ++kp) {
            const int k = tid + kp * NT;
            float4 bb = b4p[k];
            ull a0[RP], a1[RP], a2[RP], a3[RP];
            #pragma unroll
            for (int rp = 0; rp < RP; ++rp) {
                float4 wi0 = W4ih[sh_tok[2 * rp] * H + k];       // tok @ W_ih^T via gather
                float4 wi1 = W4ih[sh_tok[2 * rp + 1] * H + k];
                a0[rp] = pack2(bb.x + wi0.x, bb.x + wi1.x);
                a1[rp] = pack2(bb.y + wi0.y, bb.y + wi1.y);
                a2[rp] = pack2(bb.z + wi0.z, bb.z + wi1.z);
                a3[rp] = pack2(bb.w + wi0.w, bb.w + wi1.w);
            }
            const float4* wp = W4hh + k;
            float4 w = wp[0];
            for (int kk = 0; kk < H; ++kk) {
                float4 wnx = wp[(kk + 1) * H];   // pad covers kk=511
                ull wx = pack2(w.x, w.x), wy = pack2(w.y, w.y);
                ull wz = pack2(w.z, w.z), ww = pack2(w.w, w.w);
                #pragma unroll
                for (int rp = 0; rp < RP; ++rp) {
                    ull h2 = hp[rp * H + kk];    // broadcast LDS.64
                    a0[rp] = fma2(h2, wx, a0[rp]);
                    a1[rp] = fma2(h2, wy, a1[rp]);
                    a2[rp] = fma2(h2, wz, a2[rp]);
                    a3[rp] = fma2(h2, ww, a3[rp]);
                }
                w = wnx;
            }
            #pragma unroll
            for (int rp = 0; rp < RP; ++rp) {
                float i0, i1, f0, f1, g0, g1, o0, o1, cc0, cc1;
                unpack2(a0[rp], i0, i1);
                unpack2(a1[rp], f0, f1);
                unpack2(a2[rp], g0, g1);
                unpack2(a3[rp], o0, o1);
                unpack2(c2[kp][rp], cc0, cc1);
                float cn0 = sigf(f0) * cc0 + sigf(i0) * tanhf(g0);
                float cn1 = sigf(f1) * cc1 + sigf(i1) * tanhf(g1);
                float h0v = sigf(o0) * tanhf(cn0);
                float h1v = sigf(o1) * tanhf(cn1);
                c2[kp][rp] = pack2(cn0, cn1);
                ho[rp * H + k] = pack2(h0v, h1v);
            }
        }
        __syncthreads();

        // ---- fc: logits = relu(h_new @ W_fc^T + b_fc); write output + smem ----
        {
            const int v  = tid & (V - 1);
            const int rh = tid >> 7;          // 0 or 1: row-half
            const int p0 = rh * 4;            // rh0: pairs 0..3, rh1: pairs 4..6
            ull fa[4];
            float bv = b_fc[v];
            #pragma unroll
            for (int p = 0; p < 4; ++p) fa[p] = pack2(bv, bv);
            const float* wf = g_WTfc + v;
            const ull* hpn = (const ull*)hn + (size_t)p0 * H;
            float w = wf[0];
            for (int kk = 0; kk < H; ++kk) {
                float wn2 = wf[(kk + 1) * V];  // pad covers kk=511
                ull w2 = pack2(w, w);
                #pragma unroll
                for (int p = 0; p < 4; ++p)
                    if (p0 + p < RP) fa[p] = fma2(hpn[p * H + kk], w2, fa[p]);
                w = wn2;
            }
            #pragma unroll
            for (int p = 0; p < 4; ++p) {
                if (p0 + p >= RP) break;
                float l0, l1; unpack2(fa[p], l0, l1);
                l0 = fmaxf(l0, 0.f); l1 = fmaxf(l1, 0.f);
                int r0 = (p0 + p) * 2;
                sh_logit[r0 * V + v]       = l0;
                sh_logit[(r0 + 1) * V + v] = l1;
                int gr0 = row0 + r0;
                if (gr0     < B) out[((size_t)gr0 * STEPS + step) * V + v]       = l0;
                if (gr0 + 1 < B) out[((size_t)(gr0 + 1) * STEPS + step) * V + v] = l1;
            }
        }
        __syncthreads();

        // ---- greedy argmax per row (lowest index wins ties, matches jnp.argmax) ----
        {
            const int wid = tid >> 5, lane = tid & 31;
            for (int r = wid; r < R; r += 8) {
                float best = -1.f; int bi = 0;
                #pragma unroll
                for (int q = 0; q < 4; ++q) {
                    int vv = lane + 32 * q;
                    float val = sh_logit[r * V + vv];
                    if (val > best) { best = val; bi = vv; }
                }
                #pragma unroll
                for (int off = 16; off; off >>= 1) {
                    float ov = __shfl_xor_sync(0xffffffffu, best, off);
                    int   oi = __shfl_xor_sync(0xffffffffu, bi, off);
                    if (ov > best || (ov == best && oi < bi)) { best = ov; bi = oi; }
                }
                if (lane == 0) sh_tok[r] = bi;
            }
        }
        __syncthreads();
    }
}

// ---------------- launch ----------------
extern "C" void kernel_launch(void* const* d_in, const int* in_sizes, int n_in,
                              void* d_out, int out_size)
{
    const float* z    = (const float*)d_in[0];
    const float* W_ih = (const float*)d_in[1];
    const float* W_hh = (const float*)d_in[2];
    const float* b_ih = (const float*)d_in[3];
    const float* b_hh = (const float*)d_in[4];
    const float* W_cz = (const float*)d_in[5];
    const float* b_cz = (const float*)d_in[6];
    const float* W_fc = (const float*)d_in[7];
    const float* b_fc = (const float*)d_in[8];
    float* out = (float*)d_out;

    prep_kernel<<<1024, 256>>>(W_ih, W_hh, b_ih, b_hh, W_cz, W_fc);

    const int smem_bytes = 2 * RP * H * (int)sizeof(float2)    // h double buffer (56 KB)
                         + R * V * (int)sizeof(float)          // logits (7 KB)
                         + R * (int)sizeof(int);               // tokens
    cudaFuncSetAttribute(lstm_main, cudaFuncAttributeMaxDynamicSharedMemorySize, smem_bytes);
    lstm_main<<<(B + R - 1) / R, NT, smem_bytes>>>(z, b_cz, b_fc, out);
}